// round 10
// baseline (speedup 1.0000x reference)
#include <cuda_runtime.h>

#define VV   128
#define HH   512
#define BB   8192
#define OUTW 256   // 2*V

#define VG    8            // v's per GEMM block
#define KT    64           // k's per GEMM block
#define KS2   (HH / KT)    // 8 k-segments
#define VGN2  (VV / VG)    // 16 v-groups
#define NGEMM 128          // 16 vg x 8 ks
#define NCOPY 512          // 16 rows each
#define NBLK  (NGEMM + NCOPY)
#define THR   256

// Scratch (alloc-free rule: __device__ globals). All counters monotonic
// (never reset) -> CUDA-graph replay safe; tables identical each replay.
__device__ float    g_part[KS2 * VV * OUTW];   // 1 MB partial sums
__device__ int      g_loc[VV];
__device__ int      g_scale[VV];
__device__ unsigned g_vgdone[VGN2];            // 8 increments per vgroup/replay
__device__ unsigned g_ready = 0u;              // 16 increments per replay
__device__ unsigned g_copy_epoch = 0u;         // 512 increments per replay

// Monotone orderable key for float argmax with first-index tie-break.
__device__ __forceinline__ unsigned long long amax_key(float f, int col)
{
    unsigned int u = __float_as_uint(f);
    u = (u & 0x80000000u) ? ~u : (u | 0x80000000u);
    return ((unsigned long long)u << 32) | (unsigned long long)(127 - col);
}

__global__ void __launch_bounds__(THR, 6)
fused_kernel(const float* __restrict__ in, const float* __restrict__ W1,
             const float* __restrict__ b1, const float* __restrict__ W2,
             const float* __restrict__ b2, float* __restrict__ out)
{
    const int blk = blockIdx.x;
    const int t = threadIdx.x;
    const int wid = t >> 5, lane = t & 31;

    __shared__ __align__(16) float h[KT][VG];        // 2 KB
    __shared__ unsigned long long skey[VG * 2];      // argmax keys
    __shared__ int s_last;
    __shared__ unsigned s_target;
    __shared__ int sIdx[16];

    if (blk < NGEMM) {
        // ================= GEMM producer ====================================
        // Block (vg, ks). Thread = column c (0..255); owns acc[8] over its
        // whole 64-k segment. No intra-block k split, no staging smem.
        const int vg = blk & (VGN2 - 1);   // 0..15
        const int ks = blk >> 4;           // 0..7
        const int v0 = vg * VG;
        const int k0 = ks * KT;
        const int c = t;

        // Fill h[k][v] = relu(W1[v0+v][k0+k] + b1[k0+k]); 512 entries.
        #pragma unroll
        for (int r = 0; r < 2; ++r) {
            const int idx = t + r * THR;
            const int k = idx >> 3, v = idx & 7;
            h[k][v] = fmaxf(W1[(size_t)(v0 + v) * HH + k0 + k] + b1[k0 + k], 0.0f);
        }
        __syncthreads();

        float acc[VG];
        #pragma unroll
        for (int v = 0; v < VG; ++v) acc[v] = 0.0f;

        const float* __restrict__ w2c = W2 + (size_t)k0 * OUTW + c;
        #pragma unroll 8
        for (int k = 0; k < KT; ++k) {
            const float w = w2c[(size_t)k * OUTW];            // coalesced LDG.32
            const float4 h03 = *reinterpret_cast<const float4*>(&h[k][0]);
            const float4 h47 = *reinterpret_cast<const float4*>(&h[k][4]);
            acc[0] = fmaf(h03.x, w, acc[0]);
            acc[1] = fmaf(h03.y, w, acc[1]);
            acc[2] = fmaf(h03.z, w, acc[2]);
            acc[3] = fmaf(h03.w, w, acc[3]);
            acc[4] = fmaf(h47.x, w, acc[4]);
            acc[5] = fmaf(h47.y, w, acc[5]);
            acc[6] = fmaf(h47.z, w, acc[6]);
            acc[7] = fmaf(h47.w, w, acc[7]);
        }

        #pragma unroll
        for (int v = 0; v < VG; ++v)                          // coalesced per v
            g_part[((size_t)ks * VV + v0 + v) * OUTW + c] = acc[v];

        // ---- vgroup completion: 8th arriver reduces + argmaxes its 8 v's ---
        if (t == 0) {
            __threadfence();                                  // release partials
            const unsigned my = atomicAdd(&g_vgdone[vg], 1u);
            s_last = ((my & 7u) == 7u);
        }
        if (t < VG * 2) skey[t] = 0ULL;
        __syncthreads();

        if (s_last) {
            const float bb = b2[c];
            const int half = c >> 7;        // uniform within each warp
            const int col = c & 127;

            #pragma unroll
            for (int v = 0; v < VG; ++v) {
                float sum = bb;
                #pragma unroll
                for (int s8 = 0; s8 < KS2; ++s8)              // 8 indep loads
                    sum += g_part[((size_t)s8 * VV + v0 + v) * OUTW + c];

                // warp pre-reduce (32 cols, same half), then 1 atomic per warp
                unsigned long long key = amax_key(sum, col);
                #pragma unroll
                for (int off = 16; off > 0; off >>= 1) {
                    const unsigned long long o =
                        __shfl_xor_sync(0xFFFFFFFFu, key, off);
                    if (o > key) key = o;
                }
                if (lane == 0) atomicMax(&skey[v * 2 + half], key);
            }
            __syncthreads();

            if (t < VG) {
                g_loc[v0 + t]   = 127 - (int)(skey[t * 2]     & 0xFFFFFFFFULL);
                g_scale[v0 + t] = 127 - (int)(skey[t * 2 + 1] & 0xFFFFFFFFULL);
            }
            __syncthreads();
            if (t == 0) {
                __threadfence();                              // release tables
                atomicAdd(&g_ready, 1u);
            }
        }
    } else {
        // ================= Copy consumer: 16 rows ===========================
        const int rb = blk - NGEMM;

        // Replay-safe epoch target: tickets of replay r are [512r, 512r+512)
        // -> need g_ready >= 16*(r+1).
        if (t == 0) {
            const unsigned my = atomicAdd(&g_copy_epoch, 1u);
            s_target = ((my >> 9) + 1u) * 16u;
        }

        const int r0 = rb * 16 + wid * 2;   // 8 warps x 2 rows
        const float4* in4 = reinterpret_cast<const float4*>(in);
        float4* out4 = reinterpret_cast<float4*>(out);

        float4 a[2], c4[2];
        #pragma unroll
        for (int i = 0; i < 2; ++i) {       // front-batched: MLP 4
            const size_t base = (size_t)(r0 + i) * 64;
            a[i] = in4[base + lane];
            c4[i] = in4[base + 32 + lane];
        }

        const float4 z4 = make_float4(0.f, 0.f, 0.f, 0.f);
        #pragma unroll
        for (int i = 0; i < 2; ++i) {
            const int m0 = (a[i].x == 1.0f) | ((a[i].y == 1.0f) << 1) |
                           ((a[i].z == 1.0f) << 2) | ((a[i].w == 1.0f) << 3);
            const int m1 = (c4[i].x == 1.0f) | ((c4[i].y == 1.0f) << 1) |
                           ((c4[i].z == 1.0f) << 2) | ((c4[i].w == 1.0f) << 3);

            // one-hot -> index = sum of single nonzero lane contribution
            const int li0 = m0 ? (lane * 4 + __ffs(m0) - 1) : 0;
            const int li1 = m1 ? (lane * 4 + __ffs(m1) - 1) : 0;
            const int i0 = __reduce_add_sync(0xFFFFFFFFu, li0);
            const int i1 = __reduce_add_sync(0xFFFFFFFFu, li1);

            const size_t base = (size_t)(r0 + i) * 64;
            out4[base + lane] = a[i];
            out4[base + 32 + lane] = z4;
            if (lane == 0) sIdx[wid * 2 + i] = i0 | (i1 << 8);
        }
        __syncthreads();

        // Wait for all 16 vgroup tables of THIS replay, then scatter our rows.
        if (t == 0) {
            while ((int)(*(volatile unsigned*)&g_ready - s_target) < 0)
                __nanosleep(64);
            __threadfence();                                  // acquire tables
        }
        __syncthreads();

        if (wid == 0 && lane < 16) {
            const int row = rb * 16 + lane;
            const int pk = sIdx[lane];
            const int i0 = pk & 255;
            const int i1 = pk >> 8;
            const int l = g_loc[i0];
            const int s = g_scale[i0];
            if (s != 0) {
                const int tcol = (l + i1 * s) & (VV - 1);
                out[(size_t)row * OUTW + VV + tcol] = 1.0f;
            }
        }
    }
}

// ---------------------------------------------------------------------------
// Launch: inputs in setup_inputs() order: inputs, W1, b1, W2, b2.
// ---------------------------------------------------------------------------
extern "C" void kernel_launch(void* const* d_in, const int* in_sizes, int n_in,
                              void* d_out, int out_size)
{
    const float* in = (const float*)d_in[0];
    const float* W1 = (const float*)d_in[1];
    const float* b1 = (const float*)d_in[2];
    const float* W2 = (const float*)d_in[3];
    const float* b2 = (const float*)d_in[4];
    float* out = (float*)d_out;

    fused_kernel<<<NBLK, THR>>>(in, W1, b1, W2, b2, out);
}

// round 11
// speedup vs baseline: 1.0190x; 1.0190x over previous
#include <cuda_runtime.h>

#define VV   128
#define HH   512
#define BB   8192
#define OUTW 256   // 2*V

#define VG    8            // v's per GEMM block
#define KT    64           // k's per GEMM block
#define KS2   (HH / KT)    // 8 k-segments
#define VGN2  (VV / VG)    // 16 v-groups
#define NGEMM 128          // 16 vg x 8 ks
#define NCOPY 512          // 16 rows each
#define NBLK  (NGEMM + NCOPY)
#define THR   256

// Scratch (alloc-free rule: __device__ globals). All counters monotonic
// (never reset) -> CUDA-graph replay safe; tables identical each replay.
__device__ float    g_part[KS2 * VV * OUTW];   // 1 MB partial sums
__device__ int      g_loc[VV];
__device__ int      g_scale[VV];
__device__ unsigned g_vgdone[VGN2];            // 8 increments per vgroup/replay
__device__ unsigned g_ready = 0u;              // 16 increments per replay
__device__ unsigned g_copy_epoch = 0u;         // 512 increments per replay

// Monotone orderable key for float argmax with first-index tie-break.
__device__ __forceinline__ unsigned long long amax_key(float f, int col)
{
    unsigned int u = __float_as_uint(f);
    u = (u & 0x80000000u) ? ~u : (u | 0x80000000u);
    return ((unsigned long long)u << 32) | (unsigned long long)(127 - col);
}

__global__ void __launch_bounds__(THR, 6)
fused_kernel(const float* __restrict__ in, const float* __restrict__ W1,
             const float* __restrict__ b1, const float* __restrict__ W2,
             const float* __restrict__ b2, float* __restrict__ out)
{
    const int blk = blockIdx.x;
    const int t = threadIdx.x;
    const int wid = t >> 5, lane = t & 31;

    __shared__ __align__(16) float h[KT][VG];        // 2 KB
    __shared__ unsigned long long skey[VG * 2];      // argmax keys
    __shared__ int s_last;
    __shared__ unsigned s_target;
    __shared__ int sIdx[16];

    if (blk < NGEMM) {
        // ================= GEMM producer ====================================
        // Block (vg, ks). Thread = column c (0..255); owns acc[8] over its
        // whole 64-k segment. No intra-block k split, no staging smem.
        const int vg = blk & (VGN2 - 1);   // 0..15
        const int ks = blk >> 4;           // 0..7
        const int v0 = vg * VG;
        const int k0 = ks * KT;
        const int c = t;

        // Fill h[k][v] = relu(W1[v0+v][k0+k] + b1[k0+k]); 512 entries.
        #pragma unroll
        for (int r = 0; r < 2; ++r) {
            const int idx = t + r * THR;
            const int k = idx >> 3, v = idx & 7;
            h[k][v] = fmaxf(W1[(size_t)(v0 + v) * HH + k0 + k] + b1[k0 + k], 0.0f);
        }
        __syncthreads();

        float acc[VG];
        #pragma unroll
        for (int v = 0; v < VG; ++v) acc[v] = 0.0f;

        const float* __restrict__ w2c = W2 + (size_t)k0 * OUTW + c;
        #pragma unroll 8
        for (int k = 0; k < KT; ++k) {
            const float w = w2c[(size_t)k * OUTW];            // coalesced LDG.32
            const float4 h03 = *reinterpret_cast<const float4*>(&h[k][0]);
            const float4 h47 = *reinterpret_cast<const float4*>(&h[k][4]);
            acc[0] = fmaf(h03.x, w, acc[0]);
            acc[1] = fmaf(h03.y, w, acc[1]);
            acc[2] = fmaf(h03.z, w, acc[2]);
            acc[3] = fmaf(h03.w, w, acc[3]);
            acc[4] = fmaf(h47.x, w, acc[4]);
            acc[5] = fmaf(h47.y, w, acc[5]);
            acc[6] = fmaf(h47.z, w, acc[6]);
            acc[7] = fmaf(h47.w, w, acc[7]);
        }

        #pragma unroll
        for (int v = 0; v < VG; ++v)                          // coalesced per v
            g_part[((size_t)ks * VV + v0 + v) * OUTW + c] = acc[v];

        // ---- vgroup completion: 8th arriver reduces + argmaxes its 8 v's ---
        if (t == 0) {
            __threadfence();                                  // release partials
            const unsigned my = atomicAdd(&g_vgdone[vg], 1u);
            s_last = ((my & 7u) == 7u);
        }
        if (t < VG * 2) skey[t] = 0ULL;
        __syncthreads();

        if (s_last) {
            const float bb = b2[c];
            const int half = c >> 7;        // uniform within each warp
            const int col = c & 127;

            #pragma unroll
            for (int v = 0; v < VG; ++v) {
                float sum = bb;
                #pragma unroll
                for (int s8 = 0; s8 < KS2; ++s8)              // 8 indep loads
                    sum += g_part[((size_t)s8 * VV + v0 + v) * OUTW + c];

                // warp pre-reduce (32 cols, same half), then 1 atomic per warp
                unsigned long long key = amax_key(sum, col);
                #pragma unroll
                for (int off = 16; off > 0; off >>= 1) {
                    const unsigned long long o =
                        __shfl_xor_sync(0xFFFFFFFFu, key, off);
                    if (o > key) key = o;
                }
                if (lane == 0) atomicMax(&skey[v * 2 + half], key);
            }
            __syncthreads();

            if (t < VG) {
                g_loc[v0 + t]   = 127 - (int)(skey[t * 2]     & 0xFFFFFFFFULL);
                g_scale[v0 + t] = 127 - (int)(skey[t * 2 + 1] & 0xFFFFFFFFULL);
            }
            __syncthreads();
            if (t == 0) {
                __threadfence();                              // release tables
                atomicAdd(&g_ready, 1u);
            }
        }
    } else {
        // ================= Copy consumer: 16 rows ===========================
        const int rb = blk - NGEMM;

        // Replay-safe epoch target: tickets of replay r are [512r, 512r+512)
        // -> need g_ready >= 16*(r+1).
        if (t == 0) {
            const unsigned my = atomicAdd(&g_copy_epoch, 1u);
            s_target = ((my >> 9) + 1u) * 16u;
        }

        const int r0 = rb * 16 + wid * 2;   // 8 warps x 2 rows
        const float4* in4 = reinterpret_cast<const float4*>(in);
        float4* out4 = reinterpret_cast<float4*>(out);

        float4 a[2], c4[2];
        #pragma unroll
        for (int i = 0; i < 2; ++i) {       // front-batched: MLP 4
            const size_t base = (size_t)(r0 + i) * 64;
            a[i] = in4[base + lane];
            c4[i] = in4[base + 32 + lane];
        }

        const float4 z4 = make_float4(0.f, 0.f, 0.f, 0.f);
        #pragma unroll
        for (int i = 0; i < 2; ++i) {
            const int m0 = (a[i].x == 1.0f) | ((a[i].y == 1.0f) << 1) |
                           ((a[i].z == 1.0f) << 2) | ((a[i].w == 1.0f) << 3);
            const int m1 = (c4[i].x == 1.0f) | ((c4[i].y == 1.0f) << 1) |
                           ((c4[i].z == 1.0f) << 2) | ((c4[i].w == 1.0f) << 3);

            // one-hot -> index = sum of single nonzero lane contribution
            const int li0 = m0 ? (lane * 4 + __ffs(m0) - 1) : 0;
            const int li1 = m1 ? (lane * 4 + __ffs(m1) - 1) : 0;
            const int i0 = __reduce_add_sync(0xFFFFFFFFu, li0);
            const int i1 = __reduce_add_sync(0xFFFFFFFFu, li1);

            const size_t base = (size_t)(r0 + i) * 64;
            out4[base + lane] = a[i];
            out4[base + 32 + lane] = z4;
            if (lane == 0) sIdx[wid * 2 + i] = i0 | (i1 << 8);
        }
        __syncthreads();

        // Wait for all 16 vgroup tables of THIS replay, then scatter our rows.
        if (t == 0) {
            while ((int)(*(volatile unsigned*)&g_ready - s_target) < 0)
                __nanosleep(64);
            __threadfence();                                  // acquire tables
        }
        __syncthreads();

        if (wid == 0 && lane < 16) {
            const int row = rb * 16 + lane;
            const int pk = sIdx[lane];
            const int i0 = pk & 255;
            const int i1 = pk >> 8;
            const int l = g_loc[i0];
            const int s = g_scale[i0];
            if (s != 0) {
                const int tcol = (l + i1 * s) & (VV - 1);
                out[(size_t)row * OUTW + VV + tcol] = 1.0f;
            }
        }
    }
}

// ---------------------------------------------------------------------------
// Launch: inputs in setup_inputs() order: inputs, W1, b1, W2, b2.
// ---------------------------------------------------------------------------
extern "C" void kernel_launch(void* const* d_in, const int* in_sizes, int n_in,
                              void* d_out, int out_size)
{
    const float* in = (const float*)d_in[0];
    const float* W1 = (const float*)d_in[1];
    const float* b1 = (const float*)d_in[2];
    const float* W2 = (const float*)d_in[3];
    const float* b2 = (const float*)d_in[4];
    float* out = (float*)d_out;

    fused_kernel<<<NBLK, THR>>>(in, W1, b1, W2, b2, out);
}